// round 3
// baseline (speedup 1.0000x reference)
#include <cuda_runtime.h>

// Problem constants (fixed by setup_inputs: N=64, T=400, D=1024, M=256)
#define NTOK 25600
#define DDIM 1024
#define MCOD 256
#define ROWS_PER_BLK 64
#define KC 16
#define XLD 68  // padded row stride for xs tile (bank-conflict mitigation)

// Device scratch (allocation-free per harness rules)
__device__ float  g_enorm[MCOD * DDIM];
__device__ float  g_se[MCOD];
__device__ int    g_counts[MCOD];
__device__ double g_loss;

// ---------------------------------------------------------------------------
// Zero accumulators (must run every launch: graph replays reuse globals)
// ---------------------------------------------------------------------------
__global__ void vq_init() {
    int t = threadIdx.x;
    g_counts[t] = 0;
    if (t == 0) g_loss = 0.0;
}

// ---------------------------------------------------------------------------
// emb_norm[m] = emb[m] / (||emb[m]|| + 1e-4);  se[m] = sum(emb_norm[m]^2)
// Replicates reference rounding: fp32 sum -> sqrtf (IEEE) -> +1e-4 -> IEEE div
// ---------------------------------------------------------------------------
__global__ __launch_bounds__(256) void vq_normalize(const float* __restrict__ emb) {
    __shared__ float red[256];
    const int m = blockIdx.x;
    const int t = threadIdx.x;

    float4 v = ((const float4*)(emb + (size_t)m * DDIM))[t];
    float p = v.x * v.x + v.y * v.y + v.z * v.z + v.w * v.w;
    red[t] = p;
    __syncthreads();
    for (int s = 128; s > 0; s >>= 1) {
        if (t < s) red[t] += red[t + s];
        __syncthreads();
    }
    float denom = __fadd_rn(sqrtf(red[0]), 1e-4f);
    __syncthreads();

    float4 e;
    e.x = __fdiv_rn(v.x, denom);
    e.y = __fdiv_rn(v.y, denom);
    e.z = __fdiv_rn(v.z, denom);
    e.w = __fdiv_rn(v.w, denom);
    ((float4*)(g_enorm + (size_t)m * DDIM))[t] = e;

    float p2 = e.x * e.x + e.y * e.y + e.z * e.z + e.w * e.w;
    red[t] = p2;
    __syncthreads();
    for (int s = 128; s > 0; s >>= 1) {
        if (t < s) red[t] += red[t + s];
        __syncthreads();
    }
    if (t == 0) g_se[m] = red[0];
}

// ---------------------------------------------------------------------------
// Fused: distances GEMM (64 rows x 256 codes per block) + argmin (with
// reference's fp32 rounding + lowest-index tiebreak) + gather + ST output +
// commitment loss partial + code counts.
// Thread layout: 256 threads = 16 ty (row groups of 4) x 16 tx2 (code groups
// of 16).  acc[4 rows][16 codes] register microkernel.
// ---------------------------------------------------------------------------
__global__ __launch_bounds__(256) void vq_main(const float* __restrict__ x,
                                               const float* __restrict__ emb,
                                               float* __restrict__ out) {
    __shared__ __align__(16) float xs[KC][XLD];
    __shared__ __align__(16) float es[KC][MCOD];
    __shared__ int   sidx[ROWS_PER_BLK];
    __shared__ float sred[256];

    const int t   = threadIdx.x;
    const int ty  = t >> 4;
    const int tx2 = t & 15;
    const size_t rowBase = (size_t)blockIdx.x * ROWS_PER_BLK;

    float acc[4][16];
#pragma unroll
    for (int i = 0; i < 4; i++)
#pragma unroll
        for (int j = 0; j < 16; j++) acc[i][j] = 0.f;
    float sx[4] = {0.f, 0.f, 0.f, 0.f};

    // Tile-load mapping: x tile -> each thread one float4 (row lr, quad lq);
    // e tile -> thread t owns code row t (16 contiguous floats per chunk).
    const int lr = t >> 2;
    const int lq = t & 3;
    const float* xld = x + (rowBase + lr) * DDIM + lq * 4;
    const float* eld = g_enorm + (size_t)t * DDIM;

    for (int k0 = 0; k0 < DDIM; k0 += KC) {
        float4 xv = *(const float4*)(xld + k0);
        xs[lq * 4 + 0][lr] = xv.x;
        xs[lq * 4 + 1][lr] = xv.y;
        xs[lq * 4 + 2][lr] = xv.z;
        xs[lq * 4 + 3][lr] = xv.w;
#pragma unroll
        for (int q = 0; q < 4; q++) {
            float4 ev = *(const float4*)(eld + k0 + q * 4);
            es[q * 4 + 0][t] = ev.x;
            es[q * 4 + 1][t] = ev.y;
            es[q * 4 + 2][t] = ev.z;
            es[q * 4 + 3][t] = ev.w;
        }
        __syncthreads();

#pragma unroll
        for (int k = 0; k < KC; k++) {
            float4 xr4 = *(const float4*)&xs[k][ty * 4];
            float xr[4] = {xr4.x, xr4.y, xr4.z, xr4.w};
            sx[0] = __fmaf_rn(xr[0], xr[0], sx[0]);
            sx[1] = __fmaf_rn(xr[1], xr[1], sx[1]);
            sx[2] = __fmaf_rn(xr[2], xr[2], sx[2]);
            sx[3] = __fmaf_rn(xr[3], xr[3], sx[3]);
#pragma unroll
            for (int g = 0; g < 4; g++) {
                float4 er4 = *(const float4*)&es[k][g * 64 + tx2 * 4];
                float er[4] = {er4.x, er4.y, er4.z, er4.w};
#pragma unroll
                for (int i = 0; i < 4; i++)
#pragma unroll
                    for (int j = 0; j < 4; j++)
                        acc[i][g * 4 + j] = __fmaf_rn(xr[i], er[j], acc[i][g * 4 + j]);
            }
        }
        __syncthreads();
    }

    // Per-thread argmin over its 16 codes using reference rounding:
    //   d = fl( fl(se + sx) - fl(2*dot) ), lowest index wins ties.
    float bestD[4] = {3.4e38f, 3.4e38f, 3.4e38f, 3.4e38f};
    int   bestI[4] = {0, 0, 0, 0};
#pragma unroll
    for (int g = 0; g < 4; g++) {
#pragma unroll
        for (int j = 0; j < 4; j++) {
            const int cod = g * 64 + tx2 * 4 + j;
            const float sev = g_se[cod];
#pragma unroll
            for (int i = 0; i < 4; i++) {
                float d = __fsub_rn(__fadd_rn(sev, sx[i]),
                                    __fmul_rn(2.0f, acc[i][g * 4 + j]));
                if (d < bestD[i] || (d == bestD[i] && cod < bestI[i])) {
                    bestD[i] = d;
                    bestI[i] = cod;
                }
            }
        }
    }

    // Reduce across the 16 tx2 lanes (contiguous half-warp segments).
#pragma unroll
    for (int i = 0; i < 4; i++) {
        float d = bestD[i];
        int   bi = bestI[i];
        for (int off = 8; off > 0; off >>= 1) {
            float od = __shfl_down_sync(0xffffffffu, d, off, 16);
            int   oi = __shfl_down_sync(0xffffffffu, bi, off, 16);
            if (od < d || (od == d && oi < bi)) { d = od; bi = oi; }
        }
        if (tx2 == 0) sidx[ty * 4 + i] = bi;
    }
    __syncthreads();

    if (t < ROWS_PER_BLK) atomicAdd(&g_counts[sidx[t]], 1);

    // Gather + straight-through output + loss.
    // quantized_ = fl( fl( fl(x + fl(q-x)) + q ) * 0.5 )  (exactly as reference)
    float lloss = 0.f;
    for (int r = 0; r < ROWS_PER_BLK; ++r) {
        const int idx = sidx[r];
        float4 q  = ((const float4*)(emb + (size_t)idx * DDIM))[t];
        float4 xv = ((const float4*)(x + (rowBase + r) * DDIM))[t];
        float4 o;
        {
            float st = __fadd_rn(xv.x, __fsub_rn(q.x, xv.x));
            o.x = __fmul_rn(__fadd_rn(st, q.x), 0.5f);
            float dd = __fsub_rn(xv.x, q.x);
            lloss = __fmaf_rn(dd, dd, lloss);
        }
        {
            float st = __fadd_rn(xv.y, __fsub_rn(q.y, xv.y));
            o.y = __fmul_rn(__fadd_rn(st, q.y), 0.5f);
            float dd = __fsub_rn(xv.y, q.y);
            lloss = __fmaf_rn(dd, dd, lloss);
        }
        {
            float st = __fadd_rn(xv.z, __fsub_rn(q.z, xv.z));
            o.z = __fmul_rn(__fadd_rn(st, q.z), 0.5f);
            float dd = __fsub_rn(xv.z, q.z);
            lloss = __fmaf_rn(dd, dd, lloss);
        }
        {
            float st = __fadd_rn(xv.w, __fsub_rn(q.w, xv.w));
            o.w = __fmul_rn(__fadd_rn(st, q.w), 0.5f);
            float dd = __fsub_rn(xv.w, q.w);
            lloss = __fmaf_rn(dd, dd, lloss);
        }
        ((float4*)out)[(rowBase + r) * (DDIM / 4) + t] = o;
    }

    sred[t] = lloss;
    __syncthreads();
    for (int s = 128; s > 0; s >>= 1) {
        if (t < s) sred[t] += sred[t + s];
        __syncthreads();
    }
    if (t == 0) atomicAdd(&g_loss, (double)sred[0]);
}

// ---------------------------------------------------------------------------
// Scalars: commitment_loss = mean((x-q)^2), perplexity = exp(-sum p log(p+1e-10))
// ---------------------------------------------------------------------------
__global__ void vq_finalize(float* __restrict__ out) {
    __shared__ float red[256];
    const int t = threadIdx.x;
    float p = (float)g_counts[t] / 25600.0f;
    float term = __fmul_rn(p, logf(__fadd_rn(p, 1e-10f)));
    red[t] = term;
    __syncthreads();
    for (int s = 128; s > 0; s >>= 1) {
        if (t < s) red[t] += red[t + s];
        __syncthreads();
    }
    if (t == 0) {
        out[26214400] = (float)(g_loss / 26214400.0);
        out[26214401] = expf(-red[0]);
    }
}

extern "C" void kernel_launch(void* const* d_in, const int* in_sizes, int n_in,
                              void* d_out, int out_size) {
    const float* x   = (const float*)d_in[0];
    const float* emb = (const float*)d_in[1];
    float* out = (float*)d_out;

    vq_init<<<1, 256>>>();
    vq_normalize<<<MCOD, 256>>>(emb);
    vq_main<<<NTOK / ROWS_PER_BLK, 256>>>(x, emb, out);
    vq_finalize<<<1, 256>>>(out);
}